// round 16
// baseline (speedup 1.0000x reference)
#include <cuda_runtime.h>
#include <cuda_fp16.h>
#include <cstdint>

// ---------------- problem constants ----------------
static constexpr int MDIM = 4096;   // batch
static constexpr int NDIM = 4096;   // out features
static constexpr int KDIM = 4096;   // in features

static constexpr int BM = 128;
static constexpr int BN = 64;                // smaller N tile -> acc 32 regs -> 3 CTAs/SM
static constexpr int BK = 64;                // halves per stage (128B rows)
static constexpr int THREADS = 256;          // 8 warps: 4 (m) x 2 (n), warp tile 32x32
static constexpr int KITERS  = KDIM / BK;    // 64

static constexpr uint32_t ASTAGE = BM * BK * 2;            // 16 KB
static constexpr uint32_t BSTAGE = BN * BK * 2;            // 8 KB
static constexpr uint32_t SLOT   = ASTAGE + BSTAGE;        // 24 KB
static constexpr uint32_t SMEM_TOTAL = 3 * SLOT;           // 72 KB -> 3 CTAs/SM (216KB)

// ---------------- scratch (device globals: allocations are banned) ----------------
__device__ __align__(1024) __half g_wm[(size_t)NDIM * KDIM];  // fp16 masked weight
__device__ __align__(1024) __half g_xr[(size_t)MDIM * KDIM];  // fp16 x

// ---------------- sm_80-safe PTX helpers ----------------
__device__ __forceinline__ uint32_t smem_u32(const void* p) {
    uint32_t a;
    asm("{ .reg .u64 t; cvta.to.shared.u64 t, %1; cvt.u32.u64 %0, t; }" : "=r"(a) : "l"(p));
    return a;
}
__device__ __forceinline__ void cp_async16(uint32_t dst, const void* src) {
    asm volatile("cp.async.cg.shared.global [%0], [%1], 16;" :: "r"(dst), "l"(src) : "memory");
}
__device__ __forceinline__ void cp_commit() {
    asm volatile("cp.async.commit_group;" ::: "memory");
}
template <int N>
__device__ __forceinline__ void cp_wait() {
    asm volatile("cp.async.wait_group %0;" :: "n"(N) : "memory");
}
// Named-barrier producer/consumer split: 256 arrives + 256 syncs = 512.
__device__ __forceinline__ void bar_arrive_1() {
    asm volatile("bar.arrive 1, 512;" ::: "memory");
}
__device__ __forceinline__ void bar_sync_1() {
    asm volatile("bar.sync 1, 512;" ::: "memory");
}
__device__ __forceinline__ void ldsm_x4(uint32_t* r, uint32_t addr) {
    asm volatile("ldmatrix.sync.aligned.m8n8.x4.shared.b16 {%0,%1,%2,%3}, [%4];"
                 : "=r"(r[0]), "=r"(r[1]), "=r"(r[2]), "=r"(r[3]) : "r"(addr));
}
__device__ __forceinline__ void mma_f16(float* c, const uint32_t* a, const uint32_t* b) {
    asm volatile(
        "mma.sync.aligned.m16n8k16.row.col.f32.f16.f16.f32 "
        "{%0,%1,%2,%3}, {%4,%5,%6,%7}, {%8,%9}, {%0,%1,%2,%3};"
        : "+f"(c[0]), "+f"(c[1]), "+f"(c[2]), "+f"(c[3])
        : "r"(a[0]), "r"(a[1]), "r"(a[2]), "r"(a[3]), "r"(b[0]), "r"(b[1]));
}

// ---------------- prep: masked weight + x, both converted to fp16 RN ----------------
__global__ void prep_kernel(const float4* __restrict__ w, const float4* __restrict__ msk,
                            const float4* __restrict__ x, uint2* __restrict__ wm,
                            uint2* __restrict__ xr, int n4) {
    int stride = gridDim.x * blockDim.x;
    for (int i = blockIdx.x * blockDim.x + threadIdx.x; i < n4; i += stride) {
        float4 a = w[i], b = msk[i];
        __half2 lo = __floats2half2_rn(a.x * b.x, a.y * b.y);
        __half2 hi = __floats2half2_rn(a.z * b.z, a.w * b.w);
        uint2 o;
        o.x = *reinterpret_cast<uint32_t*>(&lo);
        o.y = *reinterpret_cast<uint32_t*>(&hi);
        wm[i] = o;
        float4 c = x[i];
        __half2 l2 = __floats2half2_rn(c.x, c.y);
        __half2 h2 = __floats2half2_rn(c.z, c.w);
        uint2 p;
        p.x = *reinterpret_cast<uint32_t*>(&l2);
        p.y = *reinterpret_cast<uint32_t*>(&h2);
        xr[i] = p;
    }
}

// ---------------- fp16 mma.sync GEMM: y = Xh * Wmh^T + bias (fp32 accum) ----------------
// R12 body (best benched) with the accumulator halved (warp tile 32x32, BN=64)
// so 3 CTAs co-reside per SM: 24 warps (6/SMSP) instead of 16 (4/SMSP). The
// R11-R15 null results showed instruction reordering can't close the 24% tensor
// gap at occ 23.5% and no throughput metric is saturated -> latency-bound; this
// attacks the latency coverage directly. Regs must land <=85 for 3 CTAs
// (enforced via __launch_bounds__), acc 64->32 frees ~40 regs vs the 126 base.
__global__ void __launch_bounds__(THREADS, 3)
gemm_kernel(const __half* __restrict__ A,   // g_xr [M][K] fp16
            const __half* __restrict__ B,   // g_wm [N][K] fp16
            const float* __restrict__ bias,
            float* __restrict__ out) {
    extern __shared__ char smem[];
    const uint32_t sbase = smem_u32(smem);
    const int tid  = threadIdx.x;
    const int lane = tid & 31;
    const int wid  = tid >> 5;
    const int wm   = wid & 3;   // warp m position (x32): 4
    const int wn   = wid >> 2;  // warp n position (x32): 2

    const int m0 = blockIdx.x * BM;
    const int n0 = blockIdx.y * BN;
    const __half* gA = A + (size_t)m0 * KDIM;
    const __half* gB = B + (size_t)n0 * KDIM;

    // -------- stage loader: 6 x 16B cp.async per thread --------
    auto load_stage = [&](int kt, uint32_t st) {
        const int kof = kt * BK;
        #pragma unroll
        for (int i = 0; i < 4; i++) {                 // A: 1024 chunks (128 rows x 8)
            int id = tid + THREADS * i;
            int r = id >> 3, c = id & 7;
            cp_async16(st + r * 128 + ((c ^ (r & 7)) << 4),
                       gA + (size_t)r * KDIM + kof + c * 8);
        }
        #pragma unroll
        for (int i = 0; i < 2; i++) {                 // B: 512 chunks (64 rows x 8)
            int id = tid + THREADS * i;
            int r = id >> 3, c = id & 7;
            cp_async16(st + ASTAGE + r * 128 + ((c ^ (r & 7)) << 4),
                       gB + (size_t)r * KDIM + kof + c * 8);
        }
    };

    // -------- per-lane fragment base addresses (relative to stage base) --------
    uint32_t afB[2], bfB[2];
    #pragma unroll
    for (int mt = 0; mt < 2; mt++) {
        int r = wm * 32 + mt * 16 + (lane & 15);
        int b = lane >> 4, k = r & 7;
        afB[mt] = r * 128 + (((b ^ (k & 1)) | (k & 6)) << 4);
    }
    #pragma unroll
    for (int p = 0; p < 2; p++) {
        int r = wn * 32 + p * 16 + (lane & 7) + ((lane >> 4) << 3);
        int b = (lane >> 3) & 1, k = r & 7;
        bfB[p] = (ASTAGE + r * 128) + (((b ^ (k & 1)) | (k & 6)) << 4);
    }

    float acc[2][4][4];
    #pragma unroll
    for (int mt = 0; mt < 2; mt++)
        #pragma unroll
        for (int nt = 0; nt < 4; nt++)
            #pragma unroll
            for (int i = 0; i < 4; i++) acc[mt][nt][i] = 0.0f;

    // -------- prologue: stages 0,1 in flight --------
    uint32_t stC = sbase, stN = sbase + SLOT, stL = sbase + 2 * SLOT;
    load_stage(0, stC); cp_commit();
    load_stage(1, stN); cp_commit();
    cp_wait<1>();
    __syncthreads();

    // -------- main K loop --------
    for (int kt = 0; kt < KITERS; kt++) {
        if (kt) bar_sync_1();   // all kt-1 arrives seen: stL free, stage-kt data published
        if (kt + 2 < KITERS) load_stage(kt + 2, stL);
        cp_commit();  // always commit to keep group accounting uniform

        #pragma unroll
        for (int s = 0; s < 3; s++) {                 // k16 steps 0..2
            const uint32_t sx = (uint32_t)(s << 5);
            uint32_t af[2][4], bf[4][2];
            #pragma unroll
            for (int mt = 0; mt < 2; mt++)
                ldsm_x4(af[mt], stC + (afB[mt] ^ sx));
            #pragma unroll
            for (int p = 0; p < 2; p++) {
                uint32_t t[4];
                ldsm_x4(t, stC + (bfB[p] ^ sx));
                bf[2 * p][0] = t[0];     bf[2 * p][1] = t[1];
                bf[2 * p + 1][0] = t[2]; bf[2 * p + 1][1] = t[3];
            }
            #pragma unroll
            for (int mt = 0; mt < 2; mt++)
                #pragma unroll
                for (int nt = 0; nt < 4; nt++)
                    mma_f16(acc[mt][nt], af[mt], bf[nt]);
        }

        // ----- step s=3: LDSM, publish (non-blocking), then register-only MMAs -----
        {
            const uint32_t sx = 3u << 5;
            uint32_t af[2][4], bf[4][2];
            #pragma unroll
            for (int mt = 0; mt < 2; mt++)
                ldsm_x4(af[mt], stC + (afB[mt] ^ sx));
            #pragma unroll
            for (int p = 0; p < 2; p++) {
                uint32_t t[4];
                ldsm_x4(t, stC + (bfB[p] ^ sx));
                bf[2 * p][0] = t[0];     bf[2 * p][1] = t[1];
                bf[2 * p + 1][0] = t[2]; bf[2 * p + 1][1] = t[3];
            }
            cp_wait<1>();      // my stage-(kt+1) cp.async group complete
            bar_arrive_1();    // non-blocking: reads of stC done + data landed
            #pragma unroll
            for (int mt = 0; mt < 2; mt++)
                #pragma unroll
                for (int nt = 0; nt < 4; nt++)
                    mma_f16(acc[mt][nt], af[mt], bf[nt]);
        }

        uint32_t t = stC; stC = stN; stN = stL; stL = t;
    }
    cp_wait<0>();  // drain tail groups before exit

    // -------- epilogue: bias add + float2 stores --------
    const int r  = lane >> 2;
    const int c2 = (lane & 3) * 2;
    const float* bp = bias + n0 + wn * 32;
    float* op = out + (size_t)(m0 + wm * 32) * NDIM + n0 + wn * 32;

    #pragma unroll
    for (int mt = 0; mt < 2; mt++) {
        #pragma unroll
        for (int nt = 0; nt < 4; nt++) {
            int n = nt * 8 + c2;
            float b0 = __ldg(bp + n), b1 = __ldg(bp + n + 1);
            float2 v0 = {acc[mt][nt][0] + b0, acc[mt][nt][1] + b1};
            float2 v1 = {acc[mt][nt][2] + b0, acc[mt][nt][3] + b1};
            *reinterpret_cast<float2*>(op + (size_t)(mt * 16 + r) * NDIM + n) = v0;
            *reinterpret_cast<float2*>(op + (size_t)(mt * 16 + r + 8) * NDIM + n) = v1;
        }
    }
}

// ---------------- host ----------------
extern "C" void kernel_launch(void* const* d_in, const int* in_sizes, int n_in,
                              void* d_out, int out_size) {
    const float* x    = (const float*)d_in[0];
    const float* w    = (const float*)d_in[1];
    const float* bias = (const float*)d_in[2];
    const float* msk  = (const float*)d_in[3];
    float* out = (float*)d_out;

    void* wm_ptr = nullptr;
    void* xr_ptr = nullptr;
    cudaGetSymbolAddress(&wm_ptr, g_wm);
    cudaGetSymbolAddress(&xr_ptr, g_xr);

    // prep: W*M and x converted to fp16 (same 11-bit mantissa as the tf32 path)
    int n4 = (KDIM * NDIM) / 4;
    prep_kernel<<<4096, 256>>>((const float4*)w, (const float4*)msk, (const float4*)x,
                               (uint2*)wm_ptr, (uint2*)xr_ptr, n4);

    cudaFuncSetAttribute(gemm_kernel, cudaFuncAttributeMaxDynamicSharedMemorySize,
                         (int)SMEM_TOTAL);

    // m fastest in blockIdx.x: concurrent CTAs (444) cover all 32 m-tiles for ~14
    // n-tiles -> 32MB fp16 x + active W panels stay L2-resident (L2 was at 26%).
    dim3 grid(MDIM / BM, NDIM / BN, 1);  // (32, 64)
    gemm_kernel<<<grid, THREADS, SMEM_TOTAL>>>((const __half*)xr_ptr, (const __half*)wm_ptr,
                                               bias, out);
}

// round 17
// speedup vs baseline: 1.0720x; 1.0720x over previous
#include <cuda_runtime.h>
#include <cuda_fp16.h>
#include <cstdint>

// ---------------- problem constants ----------------
static constexpr int MDIM = 4096;   // batch
static constexpr int NDIM = 4096;   // out features
static constexpr int KDIM = 4096;   // in features

static constexpr int BM = 128;
static constexpr int BN = 128;
static constexpr int BK = 64;                // halves per stage (128B rows)
static constexpr int THREADS = 256;          // 8 warps: 4 (m) x 2 (n), warp tile 32x64
static constexpr int KITERS  = KDIM / BK;    // 64

static constexpr uint32_t ASTAGE = BM * BK * 2;            // 16 KB
static constexpr uint32_t BSTAGE = BN * BK * 2;            // 16 KB
static constexpr uint32_t SLOT   = ASTAGE + BSTAGE;        // 32 KB
static constexpr uint32_t SMEM_TOTAL = 3 * SLOT;           // 96 KB -> 2 CTAs/SM

// ---------------- scratch (device globals: allocations are banned) ----------------
__device__ __align__(1024) __half g_wm[(size_t)NDIM * KDIM];  // fp16 masked weight
__device__ __align__(1024) __half g_xr[(size_t)MDIM * KDIM];  // fp16 x

// ---------------- sm_80-safe PTX helpers ----------------
__device__ __forceinline__ uint32_t smem_u32(const void* p) {
    uint32_t a;
    asm("{ .reg .u64 t; cvta.to.shared.u64 t, %1; cvt.u32.u64 %0, t; }" : "=r"(a) : "l"(p));
    return a;
}
__device__ __forceinline__ void cp_async16(uint32_t dst, const void* src) {
    asm volatile("cp.async.cg.shared.global [%0], [%1], 16;" :: "r"(dst), "l"(src) : "memory");
}
__device__ __forceinline__ void cp_commit() {
    asm volatile("cp.async.commit_group;" ::: "memory");
}
template <int N>
__device__ __forceinline__ void cp_wait() {
    asm volatile("cp.async.wait_group %0;" :: "n"(N) : "memory");
}
// Named-barrier producer/consumer split: 256 arrives + 256 syncs = 512.
__device__ __forceinline__ void bar_arrive_1() {
    asm volatile("bar.arrive 1, 512;" ::: "memory");
}
__device__ __forceinline__ void bar_sync_1() {
    asm volatile("bar.sync 1, 512;" ::: "memory");
}
__device__ __forceinline__ void ldsm_x4(uint32_t* r, uint32_t addr) {
    asm volatile("ldmatrix.sync.aligned.m8n8.x4.shared.b16 {%0,%1,%2,%3}, [%4];"
                 : "=r"(r[0]), "=r"(r[1]), "=r"(r[2]), "=r"(r[3]) : "r"(addr));
}
__device__ __forceinline__ void mma_f16(float* c, const uint32_t* a, const uint32_t* b) {
    asm volatile(
        "mma.sync.aligned.m16n8k16.row.col.f32.f16.f16.f32 "
        "{%0,%1,%2,%3}, {%4,%5,%6,%7}, {%8,%9}, {%0,%1,%2,%3};"
        : "+f"(c[0]), "+f"(c[1]), "+f"(c[2]), "+f"(c[3])
        : "r"(a[0]), "r"(a[1]), "r"(a[2]), "r"(a[3]), "r"(b[0]), "r"(b[1]));
}

// ---------------- prep: masked weight + x, both converted to fp16 RN ----------------
__global__ void prep_kernel(const float4* __restrict__ w, const float4* __restrict__ msk,
                            const float4* __restrict__ x, uint2* __restrict__ wm,
                            uint2* __restrict__ xr, int n4) {
    int stride = gridDim.x * blockDim.x;
    for (int i = blockIdx.x * blockDim.x + threadIdx.x; i < n4; i += stride) {
        float4 a = w[i], b = msk[i];
        __half2 lo = __floats2half2_rn(a.x * b.x, a.y * b.y);
        __half2 hi = __floats2half2_rn(a.z * b.z, a.w * b.w);
        uint2 o;
        o.x = *reinterpret_cast<uint32_t*>(&lo);
        o.y = *reinterpret_cast<uint32_t*>(&hi);
        wm[i] = o;
        float4 c = x[i];
        __half2 l2 = __floats2half2_rn(c.x, c.y);
        __half2 h2 = __floats2half2_rn(c.z, c.w);
        uint2 p;
        p.x = *reinterpret_cast<uint32_t*>(&l2);
        p.y = *reinterpret_cast<uint32_t*>(&h2);
        xr[i] = p;
    }
}

// ---------------- fp16 mma.sync GEMM: y = Xh * Wmh^T + bias (fp32 accum) ----------------
// R12 body (best benched: 296.4us) + warp step-rotation:
// All 4 k16 steps of a stage are resident when the barrier opens, so each warp
// may visit them in any rotation. Warps sharing an SMSP (wid and wid+4) were
// previously in lockstep -> their LDSM-wait windows coincided -> correlated
// tensor bubbles. We XOR the physical step with 2 for wid>=4 by folding
// ((wid>>2)<<6) into the per-lane base addresses (step index lives in address
// bits [5:6], disjoint from all other fields) -> ZERO inner-loop cost.
// Per-warp accumulation order stays fixed -> bitwise deterministic output.
__global__ void __launch_bounds__(THREADS, 2)
gemm_kernel(const __half* __restrict__ A,   // g_xr [M][K] fp16
            const __half* __restrict__ B,   // g_wm [N][K] fp16
            const float* __restrict__ bias,
            float* __restrict__ out) {
    extern __shared__ char smem[];
    const uint32_t sbase = smem_u32(smem);
    const int tid  = threadIdx.x;
    const int lane = tid & 31;
    const int wid  = tid >> 5;
    const int wm   = wid & 3;   // warp m position (x32): 4
    const int wn   = wid >> 2;  // warp n position (x64): 2

    const int m0 = blockIdx.x * BM;
    const int n0 = blockIdx.y * BN;
    const __half* gA = A + (size_t)m0 * KDIM;
    const __half* gB = B + (size_t)n0 * KDIM;

    // -------- stage loader: 8 x 16B cp.async per thread --------
    auto load_stage = [&](int kt, uint32_t st) {
        const int kof = kt * BK;
        #pragma unroll
        for (int i = 0; i < 4; i++) {                 // A: 1024 chunks (128 rows x 8)
            int id = tid + THREADS * i;
            int r = id >> 3, c = id & 7;
            cp_async16(st + r * 128 + ((c ^ (r & 7)) << 4),
                       gA + (size_t)r * KDIM + kof + c * 8);
        }
        #pragma unroll
        for (int i = 0; i < 4; i++) {                 // B: 1024 chunks
            int id = tid + THREADS * i;
            int r = id >> 3, c = id & 7;
            cp_async16(st + ASTAGE + r * 128 + ((c ^ (r & 7)) << 4),
                       gB + (size_t)r * KDIM + kof + c * 8);
        }
    };

    // -------- per-lane fragment base addresses (relative to stage base) --------
    // rotBits staggers SMSP-sharing warps (wid, wid+4) by 2 physical steps.
    const uint32_t rotBits = (uint32_t)((wid >> 2) & 1) << 6;
    uint32_t afB[2], bfB[4];
    #pragma unroll
    for (int mt = 0; mt < 2; mt++) {
        int r = wm * 32 + mt * 16 + (lane & 15);
        int b = lane >> 4, k = r & 7;
        afB[mt] = (r * 128 + (((b ^ (k & 1)) | (k & 6)) << 4)) ^ rotBits;
    }
    #pragma unroll
    for (int p = 0; p < 4; p++) {
        int r = wn * 64 + p * 16 + (lane & 7) + ((lane >> 4) << 3);
        int b = (lane >> 3) & 1, k = r & 7;
        bfB[p] = ((ASTAGE + r * 128) + (((b ^ (k & 1)) | (k & 6)) << 4)) ^ rotBits;
    }

    float acc[2][8][4];
    #pragma unroll
    for (int mt = 0; mt < 2; mt++)
        #pragma unroll
        for (int nt = 0; nt < 8; nt++)
            #pragma unroll
            for (int i = 0; i < 4; i++) acc[mt][nt][i] = 0.0f;

    // -------- prologue: stages 0,1 in flight --------
    uint32_t stC = sbase, stN = sbase + SLOT, stL = sbase + 2 * SLOT;
    load_stage(0, stC); cp_commit();
    load_stage(1, stN); cp_commit();
    cp_wait<1>();
    __syncthreads();

    // -------- main K loop --------
    for (int kt = 0; kt < KITERS; kt++) {
        if (kt) bar_sync_1();   // all kt-1 arrives seen: stL free, stage-kt data published
        if (kt + 2 < KITERS) load_stage(kt + 2, stL);
        cp_commit();  // always commit to keep group accounting uniform

        #pragma unroll
        for (int s = 0; s < 3; s++) {                 // coded steps 0..2 (physical: ^rot)
            const uint32_t sx = (uint32_t)(s << 5);
            uint32_t af[2][4], bf[8][2];
            #pragma unroll
            for (int mt = 0; mt < 2; mt++)
                ldsm_x4(af[mt], stC + (afB[mt] ^ sx));
            #pragma unroll
            for (int p = 0; p < 4; p++) {
                uint32_t t[4];
                ldsm_x4(t, stC + (bfB[p] ^ sx));
                bf[2 * p][0] = t[0];     bf[2 * p][1] = t[1];
                bf[2 * p + 1][0] = t[2]; bf[2 * p + 1][1] = t[3];
            }
            #pragma unroll
            for (int mt = 0; mt < 2; mt++)
                #pragma unroll
                for (int nt = 0; nt < 8; nt++)
                    mma_f16(acc[mt][nt], af[mt], bf[nt]);
        }

        // ----- coded step 3 (warp's last): LDSM, publish, register-only MMAs -----
        {
            const uint32_t sx = 3u << 5;
            uint32_t af[2][4], bf[8][2];
            #pragma unroll
            for (int mt = 0; mt < 2; mt++)
                ldsm_x4(af[mt], stC + (afB[mt] ^ sx));
            #pragma unroll
            for (int p = 0; p < 4; p++) {
                uint32_t t[4];
                ldsm_x4(t, stC + (bfB[p] ^ sx));
                bf[2 * p][0] = t[0];     bf[2 * p][1] = t[1];
                bf[2 * p + 1][0] = t[2]; bf[2 * p + 1][1] = t[3];
            }
            cp_wait<1>();      // my stage-(kt+1) cp.async group complete
            bar_arrive_1();    // non-blocking: all 4 physical steps of stC read
            #pragma unroll
            for (int mt = 0; mt < 2; mt++)
                #pragma unroll
                for (int nt = 0; nt < 8; nt++)
                    mma_f16(acc[mt][nt], af[mt], bf[nt]);
        }

        uint32_t t = stC; stC = stN; stN = stL; stL = t;
    }
    cp_wait<0>();  // drain tail groups before exit

    // -------- epilogue: bias add + float2 stores --------
    const int r  = lane >> 2;
    const int c2 = (lane & 3) * 2;
    const float* bp = bias + n0 + wn * 64;
    float* op = out + (size_t)(m0 + wm * 32) * NDIM + n0 + wn * 64;

    #pragma unroll
    for (int mt = 0; mt < 2; mt++) {
        #pragma unroll
        for (int nt = 0; nt < 8; nt++) {
            int n = nt * 8 + c2;
            float b0 = __ldg(bp + n), b1 = __ldg(bp + n + 1);
            float2 v0 = {acc[mt][nt][0] + b0, acc[mt][nt][1] + b1};
            float2 v1 = {acc[mt][nt][2] + b0, acc[mt][nt][3] + b1};
            *reinterpret_cast<float2*>(op + (size_t)(mt * 16 + r) * NDIM + n) = v0;
            *reinterpret_cast<float2*>(op + (size_t)(mt * 16 + r + 8) * NDIM + n) = v1;
        }
    }
}

// ---------------- host ----------------
extern "C" void kernel_launch(void* const* d_in, const int* in_sizes, int n_in,
                              void* d_out, int out_size) {
    const float* x    = (const float*)d_in[0];
    const float* w    = (const float*)d_in[1];
    const float* bias = (const float*)d_in[2];
    const float* msk  = (const float*)d_in[3];
    float* out = (float*)d_out;

    void* wm_ptr = nullptr;
    void* xr_ptr = nullptr;
    cudaGetSymbolAddress(&wm_ptr, g_wm);
    cudaGetSymbolAddress(&xr_ptr, g_xr);

    // prep: W*M and x converted to fp16 (same 11-bit mantissa as the tf32 path)
    int n4 = (KDIM * NDIM) / 4;
    prep_kernel<<<4096, 256>>>((const float4*)w, (const float4*)msk, (const float4*)x,
                               (uint2*)wm_ptr, (uint2*)xr_ptr, n4);

    cudaFuncSetAttribute(gemm_kernel, cudaFuncAttributeMaxDynamicSharedMemorySize,
                         (int)SMEM_TOTAL);

    // m fastest in blockIdx.x: x panels stay L2-hot (L2 26%, DRAM 5%).
    dim3 grid(MDIM / BM, NDIM / BN, 1);  // (32, 32)
    gemm_kernel<<<grid, THREADS, SMEM_TOTAL>>>((const __half*)xr_ptr, (const __half*)wm_ptr,
                                               bias, out);
}